// round 13
// baseline (speedup 1.0000x reference)
#include <cuda_runtime.h>
#include <cstdint>

// B=4, P2=64, TOPK=16, W2=49, C_KV=512
// r_idx: int32 (B, P2, TOPK) [reference declares int64 but JAX x64-off emits int32]
// kv:    float32 (B, P2, W2, C_KV)
// out:   float32 (B, P2, TOPK, W2, C_KV)
//
// A/B probe on the final kernel: __stwt (write-through) instead of __stcs.
// The 411MB output stream has zero reuse; skipping L2 allocation for it may
// deepen the DRAM write pipeline. Everything else identical to the 63.4us
// roofline kernel (448 threads x 14 float4, one block per region).

#define B_    4
#define P2_   64
#define TOPK_ 16
#define W2_   49
#define CKV_  512

#define THREADS_    448
#define PER_THREAD_ 14
#define REGION_F4   ((W2_ * CKV_) / 4)      // 6272
#define N_REGIONS   (B_ * P2_ * TOPK_)      // 4096

__global__ void __launch_bounds__(THREADS_, 2) kv_gather_kernel(
    const int*    __restrict__ r_idx,
    const float4* __restrict__ kv,
    float4*       __restrict__ out)
{
    const int region = blockIdx.x;              // 0..4095 = (b, p, k) flattened
    const int b = region >> 10;                 // region / (P2*TOPK)

    int r = __ldg(&r_idx[region]);
    r = min(max(r, 0), P2_ - 1);                // safety clamp (ALU is idle anyway)

    const float4* __restrict__ src = kv  + (long long)(b * P2_ + r) * REGION_F4;
    float4*       __restrict__ dst = out + (long long)region * REGION_F4;

    const int t = threadIdx.x;

    float4 v[PER_THREAD_];
#pragma unroll
    for (int i = 0; i < PER_THREAD_; i++)
        v[i] = __ldg(&src[t + i * THREADS_]);

#pragma unroll
    for (int i = 0; i < PER_THREAD_; i++)
        __stwt(&dst[t + i * THREADS_], v[i]);   // write-through: no L2 allocation
}

extern "C" void kernel_launch(void* const* d_in, const int* in_sizes, int n_in,
                              void* d_out, int out_size)
{
    const int*    r_idx = (const int*)d_in[0];
    const float4* kv    = (const float4*)d_in[1];
    float4*       out   = (float4*)d_out;

    kv_gather_kernel<<<N_REGIONS, THREADS_>>>(r_idx, kv, out);
}

// round 14
// speedup vs baseline: 1.0358x; 1.0358x over previous
#include <cuda_runtime.h>
#include <cstdint>

// B=4, P2=64, TOPK=16, W2=49, C_KV=512
// r_idx: int32 (B, P2, TOPK) [reference declares int64 but JAX x64-off emits int32]
// kv:    float32 (B, P2, W2, C_KV)
// out:   float32 (B, P2, TOPK, W2, C_KV)
//
// FINAL kernel: direct per-thread gather at the HBM write-stream roofline.
// Region = W2*CKV = 25088 floats = 6272 float4 = 448 threads * 14 float4.
// One block per region (grid=4096); 14 independent LDG.128 in flight per
// thread (front-batched by ptxas), then 14 evict-first STG.128.
//
// Roofline evidence (8 mechanisms, all 63.4-65.5us @ 73-75% dram_cycles_active,
// identical ~400MB integrated DRAM traffic = the algorithmic floor):
//   direct STG (.cs and .wt), persistent CTAs, 3-CTA occupancy, inverted
//   multicast (STG x2 + TMA), all-TMA direct, double-depth TMA.
// ~5.9TB/s is the HBM3e pure-write-stream ceiling on this part; no kernel
// lever changes the traffic floor or the drain rate.

#define B_    4
#define P2_   64
#define TOPK_ 16
#define W2_   49
#define CKV_  512

#define THREADS_    448
#define PER_THREAD_ 14
#define REGION_F4   ((W2_ * CKV_) / 4)      // 6272
#define N_REGIONS   (B_ * P2_ * TOPK_)      // 4096

__global__ void __launch_bounds__(THREADS_, 2) kv_gather_kernel(
    const int*    __restrict__ r_idx,
    const float4* __restrict__ kv,
    float4*       __restrict__ out)
{
    const int region = blockIdx.x;              // 0..4095 = (b, p, k) flattened
    const int b = region >> 10;                 // region / (P2*TOPK)

    int r = __ldg(&r_idx[region]);
    r = min(max(r, 0), P2_ - 1);                // safety clamp (ALU is idle anyway)

    const float4* __restrict__ src = kv  + (long long)(b * P2_ + r) * REGION_F4;
    float4*       __restrict__ dst = out + (long long)region * REGION_F4;

    const int t = threadIdx.x;

    float4 v[PER_THREAD_];
#pragma unroll
    for (int i = 0; i < PER_THREAD_; i++)
        v[i] = __ldg(&src[t + i * THREADS_]);

#pragma unroll
    for (int i = 0; i < PER_THREAD_; i++)
        __stcs(&dst[t + i * THREADS_], v[i]);   // evict-first: keep kv L2-resident
}

extern "C" void kernel_launch(void* const* d_in, const int* in_sizes, int n_in,
                              void* d_out, int out_size)
{
    const int*    r_idx = (const int*)d_in[0];
    const float4* kv    = (const float4*)d_in[1];
    float4*       out   = (float4*)d_out;

    kv_gather_kernel<<<N_REGIONS, THREADS_>>>(r_idx, kv, out);
}

// round 15
// speedup vs baseline: 1.0484x; 1.0122x over previous
#include <cuda_runtime.h>
#include <cstdint>

// B=4, P2=64, TOPK=16, W2=49, C_KV=512
// r_idx: int32 (B, P2, TOPK) [reference declares int64 but JAX x64-off emits int32]
// kv:    float32 (B, P2, W2, C_KV)
// out:   float32 (B, P2, TOPK, W2, C_KV)
//
// FINAL kernel: direct per-thread gather at the HBM write-stream roofline.
// Region = W2*CKV = 25088 floats = 6272 float4 = 448 threads * 14 float4.
// One block per region (grid=4096); 14 independent LDG.128 in flight per
// thread (front-batched by ptxas), then 14 evict-first STG.128.
//
// Roofline evidence (8 mechanisms over 14 rounds, all 63.4-65.5us at
// 73-75% dram_cycles_active with identical ~400MB integrated DRAM traffic,
// which is the algorithmic floor — output written exactly once, kv reads
// L2-resident):
//   direct STG (.cs and .wt), persistent CTAs, 3-CTA occupancy, inverted
//   multicast (STG x2 + TMA), all-TMA direct, double-depth TMA.
// ~5.9TB/s is the HBM3e pure-write-stream ceiling on this part; no kernel
// lever changes the traffic floor or the drain rate.

#define B_    4
#define P2_   64
#define TOPK_ 16
#define W2_   49
#define CKV_  512

#define THREADS_    448
#define PER_THREAD_ 14
#define REGION_F4   ((W2_ * CKV_) / 4)      // 6272
#define N_REGIONS   (B_ * P2_ * TOPK_)      // 4096

__global__ void __launch_bounds__(THREADS_, 2) kv_gather_kernel(
    const int*    __restrict__ r_idx,
    const float4* __restrict__ kv,
    float4*       __restrict__ out)
{
    const int region = blockIdx.x;              // 0..4095 = (b, p, k) flattened
    const int b = region >> 10;                 // region / (P2*TOPK)

    int r = __ldg(&r_idx[region]);
    r = min(max(r, 0), P2_ - 1);                // safety clamp (ALU is idle anyway)

    const float4* __restrict__ src = kv  + (long long)(b * P2_ + r) * REGION_F4;
    float4*       __restrict__ dst = out + (long long)region * REGION_F4;

    const int t = threadIdx.x;

    float4 v[PER_THREAD_];
#pragma unroll
    for (int i = 0; i < PER_THREAD_; i++)
        v[i] = __ldg(&src[t + i * THREADS_]);

#pragma unroll
    for (int i = 0; i < PER_THREAD_; i++)
        __stcs(&dst[t + i * THREADS_], v[i]);   // evict-first: keep kv L2-resident
}

extern "C" void kernel_launch(void* const* d_in, const int* in_sizes, int n_in,
                              void* d_out, int out_size)
{
    const int*    r_idx = (const int*)d_in[0];
    const float4* kv    = (const float4*)d_in[1];
    float4*       out   = (float4*)d_out;

    kv_gather_kernel<<<N_REGIONS, THREADS_>>>(r_idx, kv, out);
}